// round 3
// baseline (speedup 1.0000x reference)
#include <cuda_runtime.h>
#include <mma.h>

using namespace nvcuda;

#define N_NODES 512
#define SEQ     256
#define C_IN    32
#define B_SZ    8
#define C_OUT   64
#define GDEP    3
#define BETA    0.05f

#define SLICE   (N_NODES * SEQ)              // 131072 floats per (b,c) slice
#define SLOT    (B_SZ * C_IN * SLICE)        // 33554432 floats per hop slot

// Scratch: normalized adjacency + 3 hop buffers (hop1..hop3). hop0 == X read directly.
__device__ float g_An[N_NODES * N_NODES];
__device__ float g_hops[(size_t)GDEP * SLOT];   // 402 MB static device scratch

// ---------------------------------------------------------------------------
// Kernel 1: A' = row-normalize(A + I)
// ---------------------------------------------------------------------------
__global__ void norm_kernel(const float* __restrict__ A) {
    int v = blockIdx.x;
    int tid = threadIdx.x;
    __shared__ float red[256];
    float s = 0.0f;
    for (int w = tid; w < N_NODES; w += 256) {
        float a = A[(size_t)v * N_NODES + w] + (w == v ? 1.0f : 0.0f);
        s += a;
    }
    red[tid] = s;
    __syncthreads();
    for (int off = 128; off > 0; off >>= 1) {
        if (tid < off) red[tid] += red[tid + off];
        __syncthreads();
    }
    float inv = 1.0f / red[0];
    for (int w = tid; w < N_NODES; w += 256) {
        float a = A[(size_t)v * N_NODES + w] + (w == v ? 1.0f : 0.0f);
        g_An[(size_t)v * N_NODES + w] = a * inv;
    }
}

// ---------------------------------------------------------------------------
// Kernel 2: hop GEMM.  For each (b,c) slice: Hk = A'(512x512) @ Hprev(512x256)
// then Hnext = BETA*X + (1-BETA)*Hk.  tf32 WMMA, fp32 accumulate.
// CTA tile: 128 (rows v) x 64 (cols l).  8 warps, warp tile 32x32, frags 2x2.
// grid: (16 tiles, 256 slices), 256 threads.
// ---------------------------------------------------------------------------
__global__ void hop_kernel(const float* __restrict__ X, int src_slot, int dst_slot) {
    const float* __restrict__ src = (src_slot < 0) ? X : (g_hops + (size_t)src_slot * SLOT);
    float* __restrict__ dst = g_hops + (size_t)dst_slot * SLOT;

    const int bc = blockIdx.y;
    const int mt = blockIdx.x & 3;       // 4 row tiles of 128
    const int nt = blockIdx.x >> 2;      // 4 col tiles of 64
    const size_t sbase = (size_t)bc * SLICE;
    const int v0 = mt * 128;
    const int l0 = nt * 64;

    __shared__ __align__(16) float smem[8704];     // 34.8 KB
    float* As = smem;            // [128][36]
    float* Bs = smem + 4608;     // [32][68]

    const int tid = threadIdx.x;
    const int wid = tid >> 5;
    const int warp_m = wid & 3;          // 4 warps along rows (32 each)
    const int warp_n = wid >> 2;         // 2 warps along cols (32 each)

    wmma::fragment<wmma::accumulator, 16, 16, 8, float> acc[2][2];
#pragma unroll
    for (int i = 0; i < 2; i++)
#pragma unroll
        for (int j = 0; j < 2; j++)
            wmma::fill_fragment(acc[i][j], 0.0f);

    for (int k0 = 0; k0 < N_NODES; k0 += 32) {
        // Load A' tile: rows v0..+127, cols k0..+31  (4096 floats)
#pragma unroll
        for (int p = 0; p < 4; p++) {
            int r = p * 32 + (tid >> 3);
            int c = (tid & 7) * 4;
            float4 v = *(const float4*)(g_An + (size_t)(v0 + r) * N_NODES + k0 + c);
            v.x = wmma::__float_to_tf32(v.x);
            v.y = wmma::__float_to_tf32(v.y);
            v.z = wmma::__float_to_tf32(v.z);
            v.w = wmma::__float_to_tf32(v.w);
            *(float4*)(As + r * 36 + c) = v;
        }
        // Load H tile: rows k0..+31, cols l0..+63  (2048 floats)
#pragma unroll
        for (int p = 0; p < 2; p++) {
            int r = p * 16 + (tid >> 4);
            int c = (tid & 15) * 4;
            float4 v = *(const float4*)(src + sbase + (size_t)(k0 + r) * SEQ + l0 + c);
            v.x = wmma::__float_to_tf32(v.x);
            v.y = wmma::__float_to_tf32(v.y);
            v.z = wmma::__float_to_tf32(v.z);
            v.w = wmma::__float_to_tf32(v.w);
            *(float4*)(Bs + r * 68 + c) = v;
        }
        __syncthreads();

#pragma unroll
        for (int ks = 0; ks < 32; ks += 8) {
            wmma::fragment<wmma::matrix_a, 16, 16, 8, wmma::precision::tf32, wmma::row_major> a[2];
            wmma::fragment<wmma::matrix_b, 16, 16, 8, wmma::precision::tf32, wmma::row_major> b[2];
#pragma unroll
            for (int mi = 0; mi < 2; mi++)
                wmma::load_matrix_sync(a[mi], As + (warp_m * 32 + mi * 16) * 36 + ks, 36);
#pragma unroll
            for (int ni = 0; ni < 2; ni++)
                wmma::load_matrix_sync(b[ni], Bs + ks * 68 + warp_n * 32 + ni * 16, 68);
#pragma unroll
            for (int mi = 0; mi < 2; mi++)
#pragma unroll
                for (int ni = 0; ni < 2; ni++)
                    wmma::mma_sync(acc[mi][ni], a[mi], b[ni], acc[mi][ni]);
        }
        __syncthreads();
    }

    // Epilogue: Hnext = BETA*X + (1-BETA)*acc
    float* Cs = smem;  // [128][68] reuse
#pragma unroll
    for (int mi = 0; mi < 2; mi++)
#pragma unroll
        for (int ni = 0; ni < 2; ni++)
            wmma::store_matrix_sync(Cs + (warp_m * 32 + mi * 16) * 68 + warp_n * 32 + ni * 16,
                                    acc[mi][ni], 68, wmma::mem_row_major);
    __syncthreads();

#pragma unroll
    for (int p = 0; p < 8; p++) {
        int r = p * 16 + (tid >> 4);
        int c = (tid & 15) * 4;
        float4 cv = *(const float4*)(Cs + r * 68 + c);
        float4 xv = *(const float4*)(X + sbase + (size_t)(v0 + r) * SEQ + l0 + c);
        float4 h;
        h.x = BETA * xv.x + (1.0f - BETA) * cv.x;
        h.y = BETA * xv.y + (1.0f - BETA) * cv.y;
        h.z = BETA * xv.z + (1.0f - BETA) * cv.z;
        h.w = BETA * xv.w + (1.0f - BETA) * cv.w;
        *(float4*)(dst + sbase + (size_t)(v0 + r) * SEQ + l0 + c) = h;
    }
}

// ---------------------------------------------------------------------------
// Kernel 3: 1x1 conv.  Per batch b: out[64, 131072] = W[64,128] @ Hcat + bias.
// Channels 0..31 come from X, 32+ from g_hops.  CTA: 64 rows x 64 cols, K=128.
// grid: (2048 col tiles, 8 batches), 256 threads.
// ---------------------------------------------------------------------------
__global__ void conv_kernel(const float* __restrict__ X, const float* __restrict__ W,
                            const float* __restrict__ bias, float* __restrict__ out) {
    const int b = blockIdx.y;
    const int col0 = blockIdx.x * 64;

    __shared__ __align__(16) float smem[10624];    // 42.5 KB
    float* Ws = smem;            // [64][132]
    float* Bs = smem + 8448;     // [32][68]

    const int tid = threadIdx.x;
    const int wid = tid >> 5;
    const int warp_m = wid & 3;          // 4 warps x 16 rows
    const int warp_n = wid >> 2;         // 2 warps x 32 cols

    // Load W (64x128) into smem, tf32-rounded
#pragma unroll
    for (int p = 0; p < 8; p++) {
        int r = p * 8 + (tid >> 5);
        int c = (tid & 31) * 4;
        float4 v = *(const float4*)(W + r * 128 + c);
        v.x = wmma::__float_to_tf32(v.x);
        v.y = wmma::__float_to_tf32(v.y);
        v.z = wmma::__float_to_tf32(v.z);
        v.w = wmma::__float_to_tf32(v.w);
        *(float4*)(Ws + r * 132 + c) = v;
    }

    wmma::fragment<wmma::accumulator, 16, 16, 8, float> acc[2];
    wmma::fill_fragment(acc[0], 0.0f);
    wmma::fill_fragment(acc[1], 0.0f);

    for (int k0 = 0; k0 < 4 * C_IN; k0 += 32) {
        // Load 32 channel rows x 64 cols
#pragma unroll
        for (int p = 0; p < 2; p++) {
            int r = p * 16 + (tid >> 4);
            int c = (tid & 15) * 4;
            int ch = k0 + r;
            const float* rp;
            if (ch < C_IN) {
                rp = X + ((size_t)b * C_IN + ch) * SLICE;
            } else {
                int slot = (ch >> 5) - 1;
                int cc = ch & 31;
                rp = g_hops + (size_t)slot * SLOT + ((size_t)b * C_IN + cc) * SLICE;
            }
            float4 v = *(const float4*)(rp + col0 + c);
            v.x = wmma::__float_to_tf32(v.x);
            v.y = wmma::__float_to_tf32(v.y);
            v.z = wmma::__float_to_tf32(v.z);
            v.w = wmma::__float_to_tf32(v.w);
            *(float4*)(Bs + r * 68 + c) = v;
        }
        __syncthreads();

#pragma unroll
        for (int ks = 0; ks < 32; ks += 8) {
            wmma::fragment<wmma::matrix_a, 16, 16, 8, wmma::precision::tf32, wmma::row_major> a;
            wmma::fragment<wmma::matrix_b, 16, 16, 8, wmma::precision::tf32, wmma::row_major> bb[2];
            wmma::load_matrix_sync(a, Ws + (warp_m * 16) * 132 + k0 + ks, 132);
#pragma unroll
            for (int ni = 0; ni < 2; ni++)
                wmma::load_matrix_sync(bb[ni], Bs + ks * 68 + warp_n * 32 + ni * 16, 68);
#pragma unroll
            for (int ni = 0; ni < 2; ni++)
                wmma::mma_sync(acc[ni], a, bb[ni], acc[ni]);
        }
        __syncthreads();
    }

    // Epilogue: + bias, write out
    float* Cs = smem;  // [64][68] reuse (Ws region, no longer read)
#pragma unroll
    for (int ni = 0; ni < 2; ni++)
        wmma::store_matrix_sync(Cs + (warp_m * 16) * 68 + warp_n * 32 + ni * 16,
                                acc[ni], 68, wmma::mem_row_major);
    __syncthreads();

    const size_t obase = (size_t)b * C_OUT * SLICE;
#pragma unroll
    for (int p = 0; p < 4; p++) {
        int r = p * 16 + (tid >> 4);
        int c = (tid & 15) * 4;
        float bv = bias[r];
        float4 cv = *(const float4*)(Cs + r * 68 + c);
        cv.x += bv; cv.y += bv; cv.z += bv; cv.w += bv;
        *(float4*)(out + obase + (size_t)r * SLICE + col0 + c) = cv;
    }
}

// ---------------------------------------------------------------------------
extern "C" void kernel_launch(void* const* d_in, const int* in_sizes, int n_in,
                              void* d_out, int out_size) {
    const float* X    = (const float*)d_in[0];   // [8,32,512,256]
    const float* A    = (const float*)d_in[1];   // [512,512]
    const float* W    = (const float*)d_in[2];   // [64,128]
    const float* bias = (const float*)d_in[3];   // [64]
    float* out = (float*)d_out;                  // [8,64,512,256]

    norm_kernel<<<N_NODES, 256>>>(A);

    dim3 hop_grid(16, B_SZ * C_IN);
    hop_kernel<<<hop_grid, 256>>>(X, -1, 0);   // H1 from X
    hop_kernel<<<hop_grid, 256>>>(X,  0, 1);   // H2
    hop_kernel<<<hop_grid, 256>>>(X,  1, 2);   // H3

    dim3 conv_grid(SLICE / 64, B_SZ);
    conv_kernel<<<conv_grid, 256>>>(X, W, bias, out);
}

// round 4
// speedup vs baseline: 1.0027x; 1.0027x over previous
#include <cuda_runtime.h>
#include <mma.h>

using namespace nvcuda;

#define N_NODES 512
#define SEQ     256
#define C_IN    32
#define B_SZ    8
#define C_OUT   64
#define GDEP    3
#define BETA    0.05f

#define SLICE   (N_NODES * SEQ)              // 131072 floats per (b,c) slice
#define SLOT    (B_SZ * C_IN * SLICE)        // 33554432 floats per hop slot

// Scratch: normalized adjacency + 3 hop buffers (hop1..hop3). hop0 == X read directly.
__device__ float g_An[N_NODES * N_NODES];
__device__ float g_hops[(size_t)GDEP * SLOT];   // 402 MB static device scratch

// ---------------------------------------------------------------------------
// Kernel 1: A' = row-normalize(A + I)
// ---------------------------------------------------------------------------
__global__ void norm_kernel(const float* __restrict__ A) {
    int v = blockIdx.x;
    int tid = threadIdx.x;
    __shared__ float red[256];
    float s = 0.0f;
    for (int w = tid; w < N_NODES; w += 256) {
        float a = A[(size_t)v * N_NODES + w] + (w == v ? 1.0f : 0.0f);
        s += a;
    }
    red[tid] = s;
    __syncthreads();
    for (int off = 128; off > 0; off >>= 1) {
        if (tid < off) red[tid] += red[tid + off];
        __syncthreads();
    }
    float inv = 1.0f / red[0];
    for (int w = tid; w < N_NODES; w += 256) {
        float a = A[(size_t)v * N_NODES + w] + (w == v ? 1.0f : 0.0f);
        g_An[(size_t)v * N_NODES + w] = a * inv;
    }
}

// ---------------------------------------------------------------------------
// Kernel 2: hop GEMM.  For each (b,c) slice: Hk = A'(512x512) @ Hprev(512x256)
// then Hnext = BETA*X + (1-BETA)*Hk.  tf32 WMMA, fp32 accumulate.
// CTA tile: 128 (rows v) x 64 (cols l).  8 warps, warp tile 32x32, frags 2x2.
// grid: (16 tiles, 256 slices), 256 threads.
// ---------------------------------------------------------------------------
__global__ void hop_kernel(const float* __restrict__ X, int src_slot, int dst_slot) {
    const float* __restrict__ src = (src_slot < 0) ? X : (g_hops + (size_t)src_slot * SLOT);
    float* __restrict__ dst = g_hops + (size_t)dst_slot * SLOT;

    const int bc = blockIdx.y;
    const int mt = blockIdx.x & 3;       // 4 row tiles of 128
    const int nt = blockIdx.x >> 2;      // 4 col tiles of 64
    const size_t sbase = (size_t)bc * SLICE;
    const int v0 = mt * 128;
    const int l0 = nt * 64;

    __shared__ __align__(16) float smem[8704];     // 34.8 KB
    float* As = smem;            // [128][36]
    float* Bs = smem + 4608;     // [32][68]

    const int tid = threadIdx.x;
    const int wid = tid >> 5;
    const int warp_m = wid & 3;          // 4 warps along rows (32 each)
    const int warp_n = wid >> 2;         // 2 warps along cols (32 each)

    wmma::fragment<wmma::accumulator, 16, 16, 8, float> acc[2][2];
#pragma unroll
    for (int i = 0; i < 2; i++)
#pragma unroll
        for (int j = 0; j < 2; j++)
            wmma::fill_fragment(acc[i][j], 0.0f);

    for (int k0 = 0; k0 < N_NODES; k0 += 32) {
        // Load A' tile: rows v0..+127, cols k0..+31  (4096 floats)
#pragma unroll
        for (int p = 0; p < 4; p++) {
            int r = p * 32 + (tid >> 3);
            int c = (tid & 7) * 4;
            float4 v = *(const float4*)(g_An + (size_t)(v0 + r) * N_NODES + k0 + c);
            v.x = wmma::__float_to_tf32(v.x);
            v.y = wmma::__float_to_tf32(v.y);
            v.z = wmma::__float_to_tf32(v.z);
            v.w = wmma::__float_to_tf32(v.w);
            *(float4*)(As + r * 36 + c) = v;
        }
        // Load H tile: rows k0..+31, cols l0..+63  (2048 floats)
#pragma unroll
        for (int p = 0; p < 2; p++) {
            int r = p * 16 + (tid >> 4);
            int c = (tid & 15) * 4;
            float4 v = *(const float4*)(src + sbase + (size_t)(k0 + r) * SEQ + l0 + c);
            v.x = wmma::__float_to_tf32(v.x);
            v.y = wmma::__float_to_tf32(v.y);
            v.z = wmma::__float_to_tf32(v.z);
            v.w = wmma::__float_to_tf32(v.w);
            *(float4*)(Bs + r * 68 + c) = v;
        }
        __syncthreads();

#pragma unroll
        for (int ks = 0; ks < 32; ks += 8) {
            wmma::fragment<wmma::matrix_a, 16, 16, 8, wmma::precision::tf32, wmma::row_major> a[2];
            wmma::fragment<wmma::matrix_b, 16, 16, 8, wmma::precision::tf32, wmma::row_major> b[2];
#pragma unroll
            for (int mi = 0; mi < 2; mi++)
                wmma::load_matrix_sync(a[mi], As + (warp_m * 32 + mi * 16) * 36 + ks, 36);
#pragma unroll
            for (int ni = 0; ni < 2; ni++)
                wmma::load_matrix_sync(b[ni], Bs + ks * 68 + warp_n * 32 + ni * 16, 68);
#pragma unroll
            for (int mi = 0; mi < 2; mi++)
#pragma unroll
                for (int ni = 0; ni < 2; ni++)
                    wmma::mma_sync(acc[mi][ni], a[mi], b[ni], acc[mi][ni]);
        }
        __syncthreads();
    }

    // Epilogue: Hnext = BETA*X + (1-BETA)*acc
    float* Cs = smem;  // [128][68] reuse
#pragma unroll
    for (int mi = 0; mi < 2; mi++)
#pragma unroll
        for (int ni = 0; ni < 2; ni++)
            wmma::store_matrix_sync(Cs + (warp_m * 32 + mi * 16) * 68 + warp_n * 32 + ni * 16,
                                    acc[mi][ni], 68, wmma::mem_row_major);
    __syncthreads();

#pragma unroll
    for (int p = 0; p < 8; p++) {
        int r = p * 16 + (tid >> 4);
        int c = (tid & 15) * 4;
        float4 cv = *(const float4*)(Cs + r * 68 + c);
        float4 xv = *(const float4*)(X + sbase + (size_t)(v0 + r) * SEQ + l0 + c);
        float4 h;
        h.x = BETA * xv.x + (1.0f - BETA) * cv.x;
        h.y = BETA * xv.y + (1.0f - BETA) * cv.y;
        h.z = BETA * xv.z + (1.0f - BETA) * cv.z;
        h.w = BETA * xv.w + (1.0f - BETA) * cv.w;
        *(float4*)(dst + sbase + (size_t)(v0 + r) * SEQ + l0 + c) = h;
    }
}

// ---------------------------------------------------------------------------
// Kernel 3: 1x1 conv.  Per batch b: out[64, 131072] = W[64,128] @ Hcat + bias.
// Channels 0..31 come from X, 32+ from g_hops.  CTA: 64 rows x 64 cols, K=128.
// grid: (2048 col tiles, 8 batches), 256 threads.
// ---------------------------------------------------------------------------
__global__ void conv_kernel(const float* __restrict__ X, const float* __restrict__ W,
                            const float* __restrict__ bias, float* __restrict__ out) {
    const int b = blockIdx.y;
    const int col0 = blockIdx.x * 64;

    __shared__ __align__(16) float smem[10624];    // 42.5 KB
    float* Ws = smem;            // [64][132]
    float* Bs = smem + 8448;     // [32][68]

    const int tid = threadIdx.x;
    const int wid = tid >> 5;
    const int warp_m = wid & 3;          // 4 warps x 16 rows
    const int warp_n = wid >> 2;         // 2 warps x 32 cols

    // Load W (64x128) into smem, tf32-rounded
#pragma unroll
    for (int p = 0; p < 8; p++) {
        int r = p * 8 + (tid >> 5);
        int c = (tid & 31) * 4;
        float4 v = *(const float4*)(W + r * 128 + c);
        v.x = wmma::__float_to_tf32(v.x);
        v.y = wmma::__float_to_tf32(v.y);
        v.z = wmma::__float_to_tf32(v.z);
        v.w = wmma::__float_to_tf32(v.w);
        *(float4*)(Ws + r * 132 + c) = v;
    }

    wmma::fragment<wmma::accumulator, 16, 16, 8, float> acc[2];
    wmma::fill_fragment(acc[0], 0.0f);
    wmma::fill_fragment(acc[1], 0.0f);

    for (int k0 = 0; k0 < 4 * C_IN; k0 += 32) {
        // Load 32 channel rows x 64 cols
#pragma unroll
        for (int p = 0; p < 2; p++) {
            int r = p * 16 + (tid >> 4);
            int c = (tid & 15) * 4;
            int ch = k0 + r;
            const float* rp;
            if (ch < C_IN) {
                rp = X + ((size_t)b * C_IN + ch) * SLICE;
            } else {
                int slot = (ch >> 5) - 1;
                int cc = ch & 31;
                rp = g_hops + (size_t)slot * SLOT + ((size_t)b * C_IN + cc) * SLICE;
            }
            float4 v = *(const float4*)(rp + col0 + c);
            v.x = wmma::__float_to_tf32(v.x);
            v.y = wmma::__float_to_tf32(v.y);
            v.z = wmma::__float_to_tf32(v.z);
            v.w = wmma::__float_to_tf32(v.w);
            *(float4*)(Bs + r * 68 + c) = v;
        }
        __syncthreads();

#pragma unroll
        for (int ks = 0; ks < 32; ks += 8) {
            wmma::fragment<wmma::matrix_a, 16, 16, 8, wmma::precision::tf32, wmma::row_major> a;
            wmma::fragment<wmma::matrix_b, 16, 16, 8, wmma::precision::tf32, wmma::row_major> bb[2];
            wmma::load_matrix_sync(a, Ws + (warp_m * 16) * 132 + k0 + ks, 132);
#pragma unroll
            for (int ni = 0; ni < 2; ni++)
                wmma::load_matrix_sync(bb[ni], Bs + ks * 68 + warp_n * 32 + ni * 16, 68);
#pragma unroll
            for (int ni = 0; ni < 2; ni++)
                wmma::mma_sync(acc[ni], a, bb[ni], acc[ni]);
        }
        __syncthreads();
    }

    // Epilogue: + bias, write out
    float* Cs = smem;  // [64][68] reuse (Ws region, no longer read)
#pragma unroll
    for (int ni = 0; ni < 2; ni++)
        wmma::store_matrix_sync(Cs + (warp_m * 16) * 68 + warp_n * 32 + ni * 16,
                                acc[ni], 68, wmma::mem_row_major);
    __syncthreads();

    const size_t obase = (size_t)b * C_OUT * SLICE;
#pragma unroll
    for (int p = 0; p < 4; p++) {
        int r = p * 16 + (tid >> 4);
        int c = (tid & 15) * 4;
        float bv = bias[r];
        float4 cv = *(const float4*)(Cs + r * 68 + c);
        cv.x += bv; cv.y += bv; cv.z += bv; cv.w += bv;
        *(float4*)(out + obase + (size_t)r * SLICE + col0 + c) = cv;
    }
}

// ---------------------------------------------------------------------------
extern "C" void kernel_launch(void* const* d_in, const int* in_sizes, int n_in,
                              void* d_out, int out_size) {
    const float* X    = (const float*)d_in[0];   // [8,32,512,256]
    const float* A    = (const float*)d_in[1];   // [512,512]
    const float* W    = (const float*)d_in[2];   // [64,128]
    const float* bias = (const float*)d_in[3];   // [64]
    float* out = (float*)d_out;                  // [8,64,512,256]

    norm_kernel<<<N_NODES, 256>>>(A);

    dim3 hop_grid(16, B_SZ * C_IN);
    hop_kernel<<<hop_grid, 256>>>(X, -1, 0);   // H1 from X
    hop_kernel<<<hop_grid, 256>>>(X,  0, 1);   // H2
    hop_kernel<<<hop_grid, 256>>>(X,  1, 2);   // H3

    dim3 conv_grid(SLICE / 64, B_SZ);
    conv_kernel<<<conv_grid, 256>>>(X, W, bias, out);
}

// round 5
// speedup vs baseline: 1.0034x; 1.0006x over previous
#include <cuda_runtime.h>
#include <mma.h>

using namespace nvcuda;

#define N_NODES 512
#define SEQ     256
#define C_IN    32
#define B_SZ    8
#define C_OUT   64
#define GDEP    3
#define BETA    0.05f

#define SLICE   (N_NODES * SEQ)              // 131072 floats per (b,c) slice
#define SLOT    (B_SZ * C_IN * SLICE)        // 33554432 floats per hop slot

// Scratch: normalized adjacency + 3 hop buffers (hop1..hop3). hop0 == X read directly.
__device__ float g_An[N_NODES * N_NODES];
__device__ float g_hops[(size_t)GDEP * SLOT];   // 402 MB static device scratch

// ---------------------------------------------------------------------------
// Kernel 1: A' = row-normalize(A + I)
// ---------------------------------------------------------------------------
__global__ void norm_kernel(const float* __restrict__ A) {
    int v = blockIdx.x;
    int tid = threadIdx.x;
    __shared__ float red[256];
    float s = 0.0f;
    for (int w = tid; w < N_NODES; w += 256) {
        float a = A[(size_t)v * N_NODES + w] + (w == v ? 1.0f : 0.0f);
        s += a;
    }
    red[tid] = s;
    __syncthreads();
    for (int off = 128; off > 0; off >>= 1) {
        if (tid < off) red[tid] += red[tid + off];
        __syncthreads();
    }
    float inv = 1.0f / red[0];
    for (int w = tid; w < N_NODES; w += 256) {
        float a = A[(size_t)v * N_NODES + w] + (w == v ? 1.0f : 0.0f);
        g_An[(size_t)v * N_NODES + w] = a * inv;
    }
}

// ---------------------------------------------------------------------------
// Kernel 2: hop GEMM.  For each (b,c) slice: Hk = A'(512x512) @ Hprev(512x256)
// then Hnext = BETA*X + (1-BETA)*Hk.  tf32 WMMA, fp32 accumulate.
// CTA tile: 128 (rows v) x 64 (cols l).  8 warps, warp tile 32x32, frags 2x2.
// grid: (16 tiles, 256 slices), 256 threads.
// ---------------------------------------------------------------------------
__global__ void hop_kernel(const float* __restrict__ X, int src_slot, int dst_slot) {
    const float* __restrict__ src = (src_slot < 0) ? X : (g_hops + (size_t)src_slot * SLOT);
    float* __restrict__ dst = g_hops + (size_t)dst_slot * SLOT;

    const int bc = blockIdx.y;
    const int mt = blockIdx.x & 3;       // 4 row tiles of 128
    const int nt = blockIdx.x >> 2;      // 4 col tiles of 64
    const size_t sbase = (size_t)bc * SLICE;
    const int v0 = mt * 128;
    const int l0 = nt * 64;

    __shared__ __align__(16) float smem[8704];     // 34.8 KB
    float* As = smem;            // [128][36]
    float* Bs = smem + 4608;     // [32][68]

    const int tid = threadIdx.x;
    const int wid = tid >> 5;
    const int warp_m = wid & 3;          // 4 warps along rows (32 each)
    const int warp_n = wid >> 2;         // 2 warps along cols (32 each)

    wmma::fragment<wmma::accumulator, 16, 16, 8, float> acc[2][2];
#pragma unroll
    for (int i = 0; i < 2; i++)
#pragma unroll
        for (int j = 0; j < 2; j++)
            wmma::fill_fragment(acc[i][j], 0.0f);

    for (int k0 = 0; k0 < N_NODES; k0 += 32) {
        // Load A' tile: rows v0..+127, cols k0..+31  (4096 floats)
#pragma unroll
        for (int p = 0; p < 4; p++) {
            int r = p * 32 + (tid >> 3);
            int c = (tid & 7) * 4;
            float4 v = *(const float4*)(g_An + (size_t)(v0 + r) * N_NODES + k0 + c);
            v.x = wmma::__float_to_tf32(v.x);
            v.y = wmma::__float_to_tf32(v.y);
            v.z = wmma::__float_to_tf32(v.z);
            v.w = wmma::__float_to_tf32(v.w);
            *(float4*)(As + r * 36 + c) = v;
        }
        // Load H tile: rows k0..+31, cols l0..+63  (2048 floats)
#pragma unroll
        for (int p = 0; p < 2; p++) {
            int r = p * 16 + (tid >> 4);
            int c = (tid & 15) * 4;
            float4 v = *(const float4*)(src + sbase + (size_t)(k0 + r) * SEQ + l0 + c);
            v.x = wmma::__float_to_tf32(v.x);
            v.y = wmma::__float_to_tf32(v.y);
            v.z = wmma::__float_to_tf32(v.z);
            v.w = wmma::__float_to_tf32(v.w);
            *(float4*)(Bs + r * 68 + c) = v;
        }
        __syncthreads();

#pragma unroll
        for (int ks = 0; ks < 32; ks += 8) {
            wmma::fragment<wmma::matrix_a, 16, 16, 8, wmma::precision::tf32, wmma::row_major> a[2];
            wmma::fragment<wmma::matrix_b, 16, 16, 8, wmma::precision::tf32, wmma::row_major> b[2];
#pragma unroll
            for (int mi = 0; mi < 2; mi++)
                wmma::load_matrix_sync(a[mi], As + (warp_m * 32 + mi * 16) * 36 + ks, 36);
#pragma unroll
            for (int ni = 0; ni < 2; ni++)
                wmma::load_matrix_sync(b[ni], Bs + ks * 68 + warp_n * 32 + ni * 16, 68);
#pragma unroll
            for (int mi = 0; mi < 2; mi++)
#pragma unroll
                for (int ni = 0; ni < 2; ni++)
                    wmma::mma_sync(acc[mi][ni], a[mi], b[ni], acc[mi][ni]);
        }
        __syncthreads();
    }

    // Epilogue: Hnext = BETA*X + (1-BETA)*acc
    float* Cs = smem;  // [128][68] reuse
#pragma unroll
    for (int mi = 0; mi < 2; mi++)
#pragma unroll
        for (int ni = 0; ni < 2; ni++)
            wmma::store_matrix_sync(Cs + (warp_m * 32 + mi * 16) * 68 + warp_n * 32 + ni * 16,
                                    acc[mi][ni], 68, wmma::mem_row_major);
    __syncthreads();

#pragma unroll
    for (int p = 0; p < 8; p++) {
        int r = p * 16 + (tid >> 4);
        int c = (tid & 15) * 4;
        float4 cv = *(const float4*)(Cs + r * 68 + c);
        float4 xv = *(const float4*)(X + sbase + (size_t)(v0 + r) * SEQ + l0 + c);
        float4 h;
        h.x = BETA * xv.x + (1.0f - BETA) * cv.x;
        h.y = BETA * xv.y + (1.0f - BETA) * cv.y;
        h.z = BETA * xv.z + (1.0f - BETA) * cv.z;
        h.w = BETA * xv.w + (1.0f - BETA) * cv.w;
        *(float4*)(dst + sbase + (size_t)(v0 + r) * SEQ + l0 + c) = h;
    }
}

// ---------------------------------------------------------------------------
// Kernel 3: 1x1 conv.  Per batch b: out[64, 131072] = W[64,128] @ Hcat + bias.
// Channels 0..31 come from X, 32+ from g_hops.  CTA: 64 rows x 64 cols, K=128.
// grid: (2048 col tiles, 8 batches), 256 threads.
// ---------------------------------------------------------------------------
__global__ void conv_kernel(const float* __restrict__ X, const float* __restrict__ W,
                            const float* __restrict__ bias, float* __restrict__ out) {
    const int b = blockIdx.y;
    const int col0 = blockIdx.x * 64;

    __shared__ __align__(16) float smem[10624];    // 42.5 KB
    float* Ws = smem;            // [64][132]
    float* Bs = smem + 8448;     // [32][68]

    const int tid = threadIdx.x;
    const int wid = tid >> 5;
    const int warp_m = wid & 3;          // 4 warps x 16 rows
    const int warp_n = wid >> 2;         // 2 warps x 32 cols

    // Load W (64x128) into smem, tf32-rounded
#pragma unroll
    for (int p = 0; p < 8; p++) {
        int r = p * 8 + (tid >> 5);
        int c = (tid & 31) * 4;
        float4 v = *(const float4*)(W + r * 128 + c);
        v.x = wmma::__float_to_tf32(v.x);
        v.y = wmma::__float_to_tf32(v.y);
        v.z = wmma::__float_to_tf32(v.z);
        v.w = wmma::__float_to_tf32(v.w);
        *(float4*)(Ws + r * 132 + c) = v;
    }

    wmma::fragment<wmma::accumulator, 16, 16, 8, float> acc[2];
    wmma::fill_fragment(acc[0], 0.0f);
    wmma::fill_fragment(acc[1], 0.0f);

    for (int k0 = 0; k0 < 4 * C_IN; k0 += 32) {
        // Load 32 channel rows x 64 cols
#pragma unroll
        for (int p = 0; p < 2; p++) {
            int r = p * 16 + (tid >> 4);
            int c = (tid & 15) * 4;
            int ch = k0 + r;
            const float* rp;
            if (ch < C_IN) {
                rp = X + ((size_t)b * C_IN + ch) * SLICE;
            } else {
                int slot = (ch >> 5) - 1;
                int cc = ch & 31;
                rp = g_hops + (size_t)slot * SLOT + ((size_t)b * C_IN + cc) * SLICE;
            }
            float4 v = *(const float4*)(rp + col0 + c);
            v.x = wmma::__float_to_tf32(v.x);
            v.y = wmma::__float_to_tf32(v.y);
            v.z = wmma::__float_to_tf32(v.z);
            v.w = wmma::__float_to_tf32(v.w);
            *(float4*)(Bs + r * 68 + c) = v;
        }
        __syncthreads();

#pragma unroll
        for (int ks = 0; ks < 32; ks += 8) {
            wmma::fragment<wmma::matrix_a, 16, 16, 8, wmma::precision::tf32, wmma::row_major> a;
            wmma::fragment<wmma::matrix_b, 16, 16, 8, wmma::precision::tf32, wmma::row_major> bb[2];
            wmma::load_matrix_sync(a, Ws + (warp_m * 16) * 132 + k0 + ks, 132);
#pragma unroll
            for (int ni = 0; ni < 2; ni++)
                wmma::load_matrix_sync(bb[ni], Bs + ks * 68 + warp_n * 32 + ni * 16, 68);
#pragma unroll
            for (int ni = 0; ni < 2; ni++)
                wmma::mma_sync(acc[ni], a, bb[ni], acc[ni]);
        }
        __syncthreads();
    }

    // Epilogue: + bias, write out
    float* Cs = smem;  // [64][68] reuse (Ws region, no longer read)
#pragma unroll
    for (int ni = 0; ni < 2; ni++)
        wmma::store_matrix_sync(Cs + (warp_m * 16) * 68 + warp_n * 32 + ni * 16,
                                acc[ni], 68, wmma::mem_row_major);
    __syncthreads();

    const size_t obase = (size_t)b * C_OUT * SLICE;
#pragma unroll
    for (int p = 0; p < 4; p++) {
        int r = p * 16 + (tid >> 4);
        int c = (tid & 15) * 4;
        float bv = bias[r];
        float4 cv = *(const float4*)(Cs + r * 68 + c);
        cv.x += bv; cv.y += bv; cv.z += bv; cv.w += bv;
        *(float4*)(out + obase + (size_t)r * SLICE + col0 + c) = cv;
    }
}

// ---------------------------------------------------------------------------
extern "C" void kernel_launch(void* const* d_in, const int* in_sizes, int n_in,
                              void* d_out, int out_size) {
    const float* X    = (const float*)d_in[0];   // [8,32,512,256]
    const float* A    = (const float*)d_in[1];   // [512,512]
    const float* W    = (const float*)d_in[2];   // [64,128]
    const float* bias = (const float*)d_in[3];   // [64]
    float* out = (float*)d_out;                  // [8,64,512,256]

    norm_kernel<<<N_NODES, 256>>>(A);

    dim3 hop_grid(16, B_SZ * C_IN);
    hop_kernel<<<hop_grid, 256>>>(X, -1, 0);   // H1 from X
    hop_kernel<<<hop_grid, 256>>>(X,  0, 1);   // H2
    hop_kernel<<<hop_grid, 256>>>(X,  1, 2);   // H3

    dim3 conv_grid(SLICE / 64, B_SZ);
    conv_kernel<<<conv_grid, 256>>>(X, W, bias, out);
}